// round 1
// baseline (speedup 1.0000x reference)
#include <cuda_runtime.h>
#include <cuda_bf16.h>

#define BQ 8
#define TT 2048
#define CC 512
#define HH 16
#define HSZ 32
#define BT (BQ*TT)            // 16384
#define UEL (BT*CC)           // 8388608 elements per [B,T,C] buffer
#define MIXSZ (BT*160)
#define W64SZ (BT*64)

// Scratch: xxx | mix | xw xk xv xr xg | r k v g d | w64 | y | z
__device__ float g_scratch[(size_t)13*UEL + MIXSZ + W64SZ];

// ---------------------------------------------------------------------------
// Elementwise: xxx = x + (xshift - x) * time_maa_x
// ---------------------------------------------------------------------------
__global__ void prep_xxx_kernel(const float* __restrict__ x,
                                const float* __restrict__ tmx,
                                float* __restrict__ xxx) {
    size_t i = (size_t)blockIdx.x * blockDim.x + threadIdx.x;
    int c = (int)(i & (CC - 1));
    int t = (int)((i >> 9) & (TT - 1));
    float xv = x[i];
    float xp = (t > 0) ? x[i - CC] : 0.f;
    xxx[i] = xv + (xp - xv) * tmx[c];
}

// ---------------------------------------------------------------------------
// Generic tiled SGEMM: C[M,N] = epi(A[M,K] @ B)
//   BT_MAJOR=false: B is [K,N] (NN);  BT_MAJOR=true: B is [N,K] (NT, i.e. A@B^T)
// EPI: 0 none, 1 tanh, 2 silu, 3 exp(-exp(bias[col]+v))
// M must be a multiple of 64; K a multiple of 16; N guarded.
// ---------------------------------------------------------------------------
template<bool BT_MAJOR, int EPI>
__global__ void __launch_bounds__(256) sgemm_kernel(
    const float* __restrict__ A, const float* __restrict__ Bm,
    float* __restrict__ Cout, const float* __restrict__ bias,
    int M, int N, int K)
{
    __shared__ float As[16][65];
    __shared__ float Bs[16][65];
    int tid = threadIdx.x;
    int bm = blockIdx.y * 64;
    int bn = blockIdx.x * 64;
    int tx = tid & 15, ty = tid >> 4;
    float acc[4][4] = {};
    int arow = tid >> 2, aseg = tid & 3;

    for (int k0 = 0; k0 < K; k0 += 16) {
        float4 a4 = *reinterpret_cast<const float4*>(
            A + (size_t)(bm + arow) * K + k0 + aseg * 4);
        As[aseg*4+0][arow] = a4.x; As[aseg*4+1][arow] = a4.y;
        As[aseg*4+2][arow] = a4.z; As[aseg*4+3][arow] = a4.w;

        if (BT_MAJOR) {
            int n = tid >> 2, seg = tid & 3;
            float4 b4 = make_float4(0.f, 0.f, 0.f, 0.f);
            if (bn + n < N)
                b4 = *reinterpret_cast<const float4*>(
                    Bm + (size_t)(bn + n) * K + k0 + seg * 4);
            Bs[seg*4+0][n] = b4.x; Bs[seg*4+1][n] = b4.y;
            Bs[seg*4+2][n] = b4.z; Bs[seg*4+3][n] = b4.w;
        } else {
            int kk = tid >> 4, nb = (tid & 15) * 4;
            float4 b4 = make_float4(0.f, 0.f, 0.f, 0.f);
            if (bn + nb < N)
                b4 = *reinterpret_cast<const float4*>(
                    Bm + (size_t)(k0 + kk) * N + bn + nb);
            Bs[kk][nb+0] = b4.x; Bs[kk][nb+1] = b4.y;
            Bs[kk][nb+2] = b4.z; Bs[kk][nb+3] = b4.w;
        }
        __syncthreads();

        #pragma unroll
        for (int kk = 0; kk < 16; ++kk) {
            float ar[4], br[4];
            #pragma unroll
            for (int q = 0; q < 4; ++q) ar[q] = As[kk][ty*4 + q];
            #pragma unroll
            for (int p = 0; p < 4; ++p) br[p] = Bs[kk][tx*4 + p];
            #pragma unroll
            for (int q = 0; q < 4; ++q)
                #pragma unroll
                for (int p = 0; p < 4; ++p)
                    acc[q][p] = fmaf(ar[q], br[p], acc[q][p]);
        }
        __syncthreads();
    }

    #pragma unroll
    for (int q = 0; q < 4; ++q) {
        int row = bm + ty*4 + q;
        #pragma unroll
        for (int p = 0; p < 4; ++p) {
            int col = bn + tx*4 + p;
            if (col < N) {
                float v = acc[q][p];
                if (EPI == 1) v = tanhf(v);
                else if (EPI == 2) v = v / (1.f + __expf(-v));
                else if (EPI == 3) v = __expf(-__expf(bias[col] + v));
                Cout[(size_t)row * N + col] = v;
            }
        }
    }
}

// ---------------------------------------------------------------------------
// mix back-projection + 5-way token mix:
//   x_f = x + (xshift - x) * (time_maa_f + mix[bt,f,:] @ W2[f])
// One block per bt row; mix row (160) staged in shared.
// ---------------------------------------------------------------------------
__global__ void __launch_bounds__(256) mix_combine_kernel(
    const float* __restrict__ x, const float* __restrict__ mix,
    const float* __restrict__ W2,
    const float* __restrict__ maaw, const float* __restrict__ maak,
    const float* __restrict__ maav, const float* __restrict__ maar,
    const float* __restrict__ maag,
    float* __restrict__ xw, float* __restrict__ xk, float* __restrict__ xv_,
    float* __restrict__ xr, float* __restrict__ xg)
{
    int bt = blockIdx.x;
    int t = bt & (TT - 1);
    __shared__ float sm[160];
    if (threadIdx.x < 160) sm[threadIdx.x] = mix[(size_t)bt * 160 + threadIdx.x];
    __syncthreads();

    for (int c = threadIdx.x; c < CC; c += blockDim.x) {
        size_t i = (size_t)bt * CC + c;
        float xcur = x[i];
        float xprev = (t > 0) ? x[i - CC] : 0.f;
        float xx = xprev - xcur;
        float accs[5];
        accs[0] = maaw[c]; accs[1] = maak[c]; accs[2] = maav[c];
        accs[3] = maar[c]; accs[4] = maag[c];
        #pragma unroll
        for (int f = 0; f < 5; ++f) {
            float a = accs[f];
            const float* w2p = W2 + (size_t)f * 32 * CC + c;
            const float* smp = sm + f * 32;
            #pragma unroll
            for (int dd = 0; dd < 32; ++dd)
                a = fmaf(smp[dd], w2p[(size_t)dd * CC], a);
            accs[f] = a;
        }
        xw[i]  = fmaf(xx, accs[0], xcur);
        xk[i]  = fmaf(xx, accs[1], xcur);
        xv_[i] = fmaf(xx, accs[2], xcur);
        xr[i]  = fmaf(xx, accs[3], xcur);
        xg[i]  = fmaf(xx, accs[4], xcur);
    }
}

// ---------------------------------------------------------------------------
// WKV6 scan. One block per (b,h); warp = output dim i, lane = key dim j.
// Each thread holds S[j][i]. y_i = sum_j r_j*(S_ji + u_j*k_j*v_i);
// S_ji = d_j*S_ji + k_j*v_i.
// ---------------------------------------------------------------------------
__global__ void __launch_bounds__(1024) wkv_kernel(
    const float* __restrict__ r, const float* __restrict__ k,
    const float* __restrict__ v, const float* __restrict__ d,
    const float* __restrict__ u, float* __restrict__ y)
{
    int bh = blockIdx.x;
    int b = bh / HH, h = bh % HH;
    int warp = threadIdx.x >> 5;
    int lane = threadIdx.x & 31;
    __shared__ float ys[32][32];

    float uj = u[h * HSZ + lane];
    float S = 0.f;
    size_t base = ((size_t)b * TT) * CC + h * HSZ;

    for (int t0 = 0; t0 < TT; t0 += 32) {
        #pragma unroll 4
        for (int tt = 0; tt < 32; ++tt) {
            size_t off = base + (size_t)(t0 + tt) * CC;
            float rj = r[off + lane];
            float kj = k[off + lane];
            float dj = d[off + lane];
            float vi = v[off + warp];
            float a  = kj * vi;
            float p  = rj * S + (rj * uj) * a;
            #pragma unroll
            for (int s = 16; s; s >>= 1)
                p += __shfl_xor_sync(0xffffffffu, p, s);
            S = fmaf(dj, S, a);
            if (lane == 0) ys[tt][warp] = p;
        }
        __syncthreads();
        {
            size_t off = base + (size_t)(t0 + warp) * CC;
            y[off + lane] = ys[warp][lane];
        }
        __syncthreads();
    }
}

// ---------------------------------------------------------------------------
// Per-head groupnorm (32 elems) * ln + b, then * gate. One warp per group.
// ---------------------------------------------------------------------------
__global__ void __launch_bounds__(256) gn_kernel(
    const float* __restrict__ y, const float* __restrict__ gate,
    const float* __restrict__ lnw, const float* __restrict__ lnb,
    float* __restrict__ z)
{
    int g = blockIdx.x * 8 + (threadIdx.x >> 5);
    int lane = threadIdx.x & 31;
    size_t idx = (size_t)g * 32 + lane;
    float v = y[idx];
    float s = v;
    #pragma unroll
    for (int o = 16; o; o >>= 1) s += __shfl_xor_sync(0xffffffffu, s, o);
    float mu = s * (1.f / 32.f);
    float dv = v - mu;
    float q = dv * dv;
    #pragma unroll
    for (int o = 16; o; o >>= 1) q += __shfl_xor_sync(0xffffffffu, q, o);
    float var = q * (1.f / 32.f);
    float yn = dv * rsqrtf(var + 1e-5f);
    int c = (int)(idx & (CC - 1));
    z[idx] = (yn * lnw[c] + lnb[c]) * gate[idx];
}

// ---------------------------------------------------------------------------
extern "C" void kernel_launch(void* const* d_in, const int* in_sizes, int n_in,
                              void* d_out, int out_size) {
    const float* x      = (const float*)d_in[0];
    const float* tmaa_x = (const float*)d_in[1];
    const float* tmaa_w = (const float*)d_in[2];
    const float* tmaa_k = (const float*)d_in[3];
    const float* tmaa_v = (const float*)d_in[4];
    const float* tmaa_r = (const float*)d_in[5];
    const float* tmaa_g = (const float*)d_in[6];
    const float* w1     = (const float*)d_in[7];   // (C,160)
    const float* w2     = (const float*)d_in[8];   // (5,32,C)
    const float* tdecay = (const float*)d_in[9];   // (C,)
    const float* tdw1   = (const float*)d_in[10];  // (C,64)
    const float* tdw2   = (const float*)d_in[11];  // (64,C)
    const float* faaaa  = (const float*)d_in[12];  // (H,HS)
    const float* Wr     = (const float*)d_in[13];
    const float* Wk     = (const float*)d_in[14];
    const float* Wv     = (const float*)d_in[15];
    const float* Wg     = (const float*)d_in[16];
    const float* Wo     = (const float*)d_in[17];
    const float* lnw    = (const float*)d_in[18];
    const float* lnb    = (const float*)d_in[19];
    float* out = (float*)d_out;

    float* S;
    cudaGetSymbolAddress((void**)&S, g_scratch);
    float* xxx  = S;
    float* mixb = xxx + UEL;
    float* xw   = mixb + MIXSZ;
    float* xk   = xw + UEL;
    float* xv   = xk + UEL;
    float* xr   = xv + UEL;
    float* xg   = xr + UEL;
    float* rb   = xg + UEL;
    float* kb   = rb + UEL;
    float* vb   = kb + UEL;
    float* gb   = vb + UEL;
    float* db   = gb + UEL;
    float* w64  = db + UEL;
    float* yb   = w64 + W64SZ;
    float* zb   = yb + UEL;

    // 1) xxx = x + (shift(x)-x)*maa_x
    prep_xxx_kernel<<<UEL / 256, 256>>>(x, tmaa_x, xxx);

    // 2) mix = tanh(xxx @ w1)   [BT,160]
    sgemm_kernel<false, 1><<<dim3(3, BT / 64), 256>>>(xxx, w1, mixb, nullptr, BT, 160, CC);

    // 3) 5-way mix back-projection + token mixing -> xw..xg
    mix_combine_kernel<<<BT, 256>>>(x, mixb, w2, tmaa_w, tmaa_k, tmaa_v, tmaa_r,
                                    tmaa_g, xw, xk, xv, xr, xg);

    // 4) projections (A @ W^T, W row-major [N,K])
    sgemm_kernel<true, 0><<<dim3(8, BT / 64), 256>>>(xr, Wr, rb, nullptr, BT, CC, CC);
    sgemm_kernel<true, 0><<<dim3(8, BT / 64), 256>>>(xk, Wk, kb, nullptr, BT, CC, CC);
    sgemm_kernel<true, 0><<<dim3(8, BT / 64), 256>>>(xv, Wv, vb, nullptr, BT, CC, CC);
    sgemm_kernel<true, 2><<<dim3(8, BT / 64), 256>>>(xg, Wg, gb, nullptr, BT, CC, CC);

    // 5) decay MLP: w64 = tanh(xw @ tdw1); d = exp(-exp(tdecay + w64 @ tdw2))
    sgemm_kernel<false, 1><<<dim3(1, BT / 64), 256>>>(xw, tdw1, w64, nullptr, BT, 64, CC);
    sgemm_kernel<false, 3><<<dim3(8, BT / 64), 256>>>(w64, tdw2, db, tdecay, BT, CC, 64);

    // 6) WKV6 scan
    wkv_kernel<<<BQ * HH, 1024>>>(rb, kb, vb, db, faaaa, yb);

    // 7) groupnorm * ln * gate
    gn_kernel<<<(BT * HH) / 8, 256>>>(yb, gb, lnw, lnb, zb);

    // 8) out = z @ Wo^T
    sgemm_kernel<true, 0><<<dim3(8, BT / 64), 256>>>(zb, Wo, out, nullptr, BT, CC, CC);
}

// round 3
// speedup vs baseline: 1.7358x; 1.7358x over previous
#include <cuda_runtime.h>
#include <cuda_bf16.h>
#include <cstdint>

#define BQ 8
#define TT 2048
#define CC 512
#define HH 16
#define HSZ 32
#define BT (BQ*TT)            // 16384
#define UEL ((size_t)BT*CC)   // 8388608 elements per [B,T,C] buffer

// ---------------------------------------------------------------------------
// Scratch (bytes). One big device array; no allocations anywhere.
// ---------------------------------------------------------------------------
#define SZ_F32   (UEL*4)
#define SZ_BF16  (UEL*2)
#define SZ_MIX   ((size_t)BT*160*4)
#define SZ_W64   ((size_t)BT*64*4)
#define SZ_WBF   ((size_t)CC*CC*2)

#define O_XXX   ((size_t)0)
#define O_MIX   (O_XXX + SZ_F32)
#define O_XW    (O_MIX + SZ_MIX)
#define O_W64   (O_XW + SZ_F32)
#define O_DB    (O_W64 + SZ_W64)
#define O_RB    (O_DB + SZ_F32)
#define O_KB    (O_RB + SZ_F32)
#define O_VB    (O_KB + SZ_F32)
#define O_GB    (O_VB + SZ_F32)
#define O_YB    (O_GB + SZ_F32)
#define O_KH    (O_YB + SZ_F32)
#define O_KL    (O_KH + SZ_BF16)
#define O_VH    (O_KL + SZ_BF16)
#define O_VL    (O_VH + SZ_BF16)
#define O_RH    (O_VL + SZ_BF16)
#define O_RL    (O_RH + SZ_BF16)
#define O_GH    (O_RL + SZ_BF16)
#define O_GL    (O_GH + SZ_BF16)
#define O_ZH    (O_GL + SZ_BF16)
#define O_ZL    (O_ZH + SZ_BF16)
#define O_WRH   (O_ZL + SZ_BF16)
#define O_WRL   (O_WRH + SZ_WBF)
#define O_WKH   (O_WRL + SZ_WBF)
#define O_WKL   (O_WKH + SZ_WBF)
#define O_WVH   (O_WKL + SZ_WBF)
#define O_WVL   (O_WVH + SZ_WBF)
#define O_WGH   (O_WVL + SZ_WBF)
#define O_WGL   (O_WGH + SZ_WBF)
#define O_WOH   (O_WGL + SZ_WBF)
#define O_WOL   (O_WOH + SZ_WBF)
#define SCRATCH_BYTES (O_WOL + SZ_WBF)

__device__ __align__(256) unsigned char g_scratch[SCRATCH_BYTES];

// ---------------------------------------------------------------------------
// mma.sync helpers (valid on plain compute_103 / sm_80+)
// ---------------------------------------------------------------------------
__device__ __forceinline__ uint32_t smem_u32(const void* p) {
    uint32_t a;
    asm("{ .reg .u64 t; cvta.to.shared.u64 t, %1; cvt.u32.u64 %0, t; }"
        : "=r"(a) : "l"(p));
    return a;
}

#define LDSM4(r, a) \
    asm volatile("ldmatrix.sync.aligned.m8n8.x4.shared.b16 {%0,%1,%2,%3}, [%4];" \
        : "=r"((r)[0]), "=r"((r)[1]), "=r"((r)[2]), "=r"((r)[3]) : "r"(a))

#define MMA16816(d, a, b0, b1) \
    asm volatile("mma.sync.aligned.m16n8k16.row.col.f32.bf16.bf16.f32 " \
        "{%0,%1,%2,%3}, {%4,%5,%6,%7}, {%8,%9}, {%0,%1,%2,%3};" \
        : "+f"((d)[0]), "+f"((d)[1]), "+f"((d)[2]), "+f"((d)[3]) \
        : "r"((a)[0]), "r"((a)[1]), "r"((a)[2]), "r"((a)[3]), "r"(b0), "r"(b1))

// ---------------------------------------------------------------------------
// Tensor-core GEMM via mma.sync: C[M,512] = epi(A @ W^T), split bf16 (hi/lo),
// 3 terms: Ah*Bh + Ah*Bl + Al*Bh.  Tile 128x128, K-chunk 64.
// smem rows padded to 72 bf16 (144B) -> conflict-free ldmatrix.
// EPI: 0 none, 2 silu.
// ---------------------------------------------------------------------------
#define TROWB 144                 // bytes per padded row
#define TREG  (128*TROWB)         // 18432 bytes per matrix tile
#define TG_SMEM (4*TREG)          // 73728

template<int EPI>
__global__ void __launch_bounds__(256)
tgemm_kernel(const __nv_bfloat16* __restrict__ Ah, const __nv_bfloat16* __restrict__ Al,
             const __nv_bfloat16* __restrict__ Bh, const __nv_bfloat16* __restrict__ Bl,
             float* __restrict__ C)
{
    extern __shared__ unsigned char sm[];
    uint32_t smb = smem_u32(sm);
    int tid = threadIdx.x;
    int wid = tid >> 5, lane = tid & 31;
    int bm = blockIdx.y * 128, bn = blockIdx.x * 128;
    int wm = (wid & 3) * 32, wn = (wid >> 2) * 64;

    float acc[2][8][4];
    #pragma unroll
    for (int i = 0; i < 2; ++i)
        #pragma unroll
        for (int j = 0; j < 8; ++j)
            #pragma unroll
            for (int q = 0; q < 4; ++q) acc[i][j][q] = 0.f;

    int mat = lane >> 3, r8 = lane & 7;
    int lrow = (mat & 1) * 8 + r8;    // row within 16-row tile
    int lkb  = (mat >> 1) * 16;       // byte offset within 32B k16 strip

    for (int ch = 0; ch < 8; ++ch) {
        int k0 = ch * 64;
        // Stage 4 tiles (Ah, Al, Bh, Bl): 128 rows x 64 bf16 each.
        #pragma unroll
        for (int m = 0; m < 4; ++m) {
            const __nv_bfloat16* G = (m == 0) ? Ah : (m == 1) ? Al : (m == 2) ? Bh : Bl;
            int rbase = (m < 2) ? bm : bn;
            #pragma unroll
            for (int it = 0; it < 4; ++it) {
                int idx = it * 256 + tid;
                int row = idx >> 3, seg = idx & 7;
                uint4 v = *reinterpret_cast<const uint4*>(
                    G + (size_t)(rbase + row) * 512 + k0 + seg * 8);
                *reinterpret_cast<uint4*>(sm + m * TREG + row * TROWB + seg * 16) = v;
            }
        }
        __syncthreads();

        #pragma unroll
        for (int ks = 0; ks < 4; ++ks) {
            uint32_t ah[2][4], al[2][4];
            #pragma unroll
            for (int mt = 0; mt < 2; ++mt) {
                uint32_t ra = smb + (wm + mt * 16 + lrow) * TROWB + ks * 32 + lkb;
                LDSM4(ah[mt], ra);
                LDSM4(al[mt], ra + TREG);
            }
            #pragma unroll
            for (int nt = 0; nt < 4; ++nt) {
                uint32_t rb = smb + 2 * TREG + (wn + nt * 16 + lrow) * TROWB + ks * 32 + lkb;
                uint32_t bh4[4], bl4[4];
                LDSM4(bh4, rb);
                LDSM4(bl4, rb + TREG);
                #pragma unroll
                for (int mt = 0; mt < 2; ++mt) {
                    MMA16816(acc[mt][nt*2+0], ah[mt], bh4[0], bh4[2]);
                    MMA16816(acc[mt][nt*2+1], ah[mt], bh4[1], bh4[3]);
                    MMA16816(acc[mt][nt*2+0], ah[mt], bl4[0], bl4[2]);
                    MMA16816(acc[mt][nt*2+1], ah[mt], bl4[1], bl4[3]);
                    MMA16816(acc[mt][nt*2+0], al[mt], bh4[0], bh4[2]);
                    MMA16816(acc[mt][nt*2+1], al[mt], bh4[1], bh4[3]);
                }
            }
        }
        __syncthreads();
    }

    // epilogue: direct stores
    int r0 = lane >> 2, c0 = (lane & 3) * 2;
    #pragma unroll
    for (int mt = 0; mt < 2; ++mt) {
        #pragma unroll
        for (int nt = 0; nt < 4; ++nt) {
            #pragma unroll
            for (int s = 0; s < 2; ++s) {
                float* a4 = acc[mt][nt*2+s];
                int col = bn + wn + nt * 16 + s * 8 + c0;
                int row = bm + wm + mt * 16 + r0;
                float v0 = a4[0], v1 = a4[1], v2 = a4[2], v3 = a4[3];
                if (EPI == 2) {
                    v0 = v0 / (1.f + __expf(-v0));
                    v1 = v1 / (1.f + __expf(-v1));
                    v2 = v2 / (1.f + __expf(-v2));
                    v3 = v3 / (1.f + __expf(-v3));
                }
                *reinterpret_cast<float2*>(C + (size_t)row * 512 + col)       = make_float2(v0, v1);
                *reinterpret_cast<float2*>(C + (size_t)(row + 8) * 512 + col) = make_float2(v2, v3);
            }
        }
    }
}

// ---------------------------------------------------------------------------
// Elementwise: xxx = x + (xshift - x) * time_maa_x
// ---------------------------------------------------------------------------
__global__ void prep_xxx_kernel(const float* __restrict__ x,
                                const float* __restrict__ tmx,
                                float* __restrict__ xxx) {
    size_t i = (size_t)blockIdx.x * blockDim.x + threadIdx.x;
    int c = (int)(i & (CC - 1));
    int t = (int)((i >> 9) & (TT - 1));
    float xv = x[i];
    float xp = (t > 0) ? x[i - CC] : 0.f;
    xxx[i] = xv + (xp - xv) * tmx[c];
}

// ---------------------------------------------------------------------------
// SIMT SGEMM (small GEMMs: mix 160-wide, decay MLP)
// ---------------------------------------------------------------------------
template<bool BT_MAJOR, int EPI>
__global__ void __launch_bounds__(256) sgemm_kernel(
    const float* __restrict__ A, const float* __restrict__ Bm,
    float* __restrict__ Cout, const float* __restrict__ bias,
    int M, int N, int K)
{
    __shared__ float As[16][65];
    __shared__ float Bs[16][65];
    int tid = threadIdx.x;
    int bm = blockIdx.y * 64;
    int bn = blockIdx.x * 64;
    int tx = tid & 15, ty = tid >> 4;
    float acc[4][4] = {};
    int arow = tid >> 2, aseg = tid & 3;

    for (int k0 = 0; k0 < K; k0 += 16) {
        float4 a4 = *reinterpret_cast<const float4*>(
            A + (size_t)(bm + arow) * K + k0 + aseg * 4);
        As[aseg*4+0][arow] = a4.x; As[aseg*4+1][arow] = a4.y;
        As[aseg*4+2][arow] = a4.z; As[aseg*4+3][arow] = a4.w;

        if (BT_MAJOR) {
            int n = tid >> 2, seg = tid & 3;
            float4 b4 = make_float4(0.f, 0.f, 0.f, 0.f);
            if (bn + n < N)
                b4 = *reinterpret_cast<const float4*>(
                    Bm + (size_t)(bn + n) * K + k0 + seg * 4);
            Bs[seg*4+0][n] = b4.x; Bs[seg*4+1][n] = b4.y;
            Bs[seg*4+2][n] = b4.z; Bs[seg*4+3][n] = b4.w;
        } else {
            int kk = tid >> 4, nb = (tid & 15) * 4;
            float4 b4 = make_float4(0.f, 0.f, 0.f, 0.f);
            if (bn + nb < N)
                b4 = *reinterpret_cast<const float4*>(
                    Bm + (size_t)(k0 + kk) * N + bn + nb);
            Bs[kk][nb+0] = b4.x; Bs[kk][nb+1] = b4.y;
            Bs[kk][nb+2] = b4.z; Bs[kk][nb+3] = b4.w;
        }
        __syncthreads();

        #pragma unroll
        for (int kk = 0; kk < 16; ++kk) {
            float ar[4], br[4];
            #pragma unroll
            for (int q = 0; q < 4; ++q) ar[q] = As[kk][ty*4 + q];
            #pragma unroll
            for (int p = 0; p < 4; ++p) br[p] = Bs[kk][tx*4 + p];
            #pragma unroll
            for (int q = 0; q < 4; ++q)
                #pragma unroll
                for (int p = 0; p < 4; ++p)
                    acc[q][p] = fmaf(ar[q], br[p], acc[q][p]);
        }
        __syncthreads();
    }

    #pragma unroll
    for (int q = 0; q < 4; ++q) {
        int row = bm + ty*4 + q;
        #pragma unroll
        for (int p = 0; p < 4; ++p) {
            int col = bn + tx*4 + p;
            if (col < N) {
                float v = acc[q][p];
                if (EPI == 1) v = tanhf(v);
                else if (EPI == 3) v = __expf(-__expf(bias[col] + v));
                Cout[(size_t)row * N + col] = v;
            }
        }
    }
}

// ---------------------------------------------------------------------------
// split helper
// ---------------------------------------------------------------------------
__device__ __forceinline__ void wsplit(float v, __nv_bfloat16* hi, __nv_bfloat16* lo, size_t i) {
    __nv_bfloat16 h = __float2bfloat16(v);
    hi[i] = h;
    lo[i] = __float2bfloat16(v - __bfloat162float(h));
}

// ---------------------------------------------------------------------------
// mix back-projection + 5-way token mix. Block = 16 bt rows x 512 c.
// W2 read coalesced once per block; mix rows and x staged in smem.
// ---------------------------------------------------------------------------
__global__ void __launch_bounds__(512) mix_combine_kernel(
    const float* __restrict__ x, const float* __restrict__ mix,
    const float* __restrict__ W2,
    const float* __restrict__ maaw, const float* __restrict__ maak,
    const float* __restrict__ maav, const float* __restrict__ maar,
    const float* __restrict__ maag,
    float* __restrict__ xw,
    __nv_bfloat16* __restrict__ kh, __nv_bfloat16* __restrict__ kl,
    __nv_bfloat16* __restrict__ vh, __nv_bfloat16* __restrict__ vl,
    __nv_bfloat16* __restrict__ rh, __nv_bfloat16* __restrict__ rl,
    __nv_bfloat16* __restrict__ gh, __nv_bfloat16* __restrict__ gl)
{
    __shared__ float s_mix[16][160];
    __shared__ float s_x[16][512];
    __shared__ float s_xp0[512];
    int bt0 = blockIdx.x * 16;
    int c = threadIdx.x;

    for (int i = threadIdx.x; i < 16 * 160; i += 512)
        s_mix[i / 160][i % 160] = mix[(size_t)bt0 * 160 + i];
    #pragma unroll
    for (int row = 0; row < 16; ++row)
        s_x[row][c] = x[(size_t)(bt0 + row) * 512 + c];
    s_xp0[c] = (bt0 & (TT - 1)) ? x[(size_t)(bt0 - 1) * 512 + c] : 0.f;
    __syncthreads();

    float maa[5];
    maa[0] = maaw[c]; maa[1] = maak[c]; maa[2] = maav[c];
    maa[3] = maar[c]; maa[4] = maag[c];

    #pragma unroll
    for (int f = 0; f < 5; ++f) {
        float acc[16];
        #pragma unroll
        for (int row = 0; row < 16; ++row) acc[row] = 0.f;
        #pragma unroll 8
        for (int dd = 0; dd < 32; ++dd) {
            float w = W2[(size_t)(f * 32 + dd) * 512 + c];
            #pragma unroll
            for (int row = 0; row < 16; ++row)
                acc[row] = fmaf(s_mix[row][f * 32 + dd], w, acc[row]);
        }
        #pragma unroll
        for (int row = 0; row < 16; ++row) {
            size_t gi = (size_t)(bt0 + row) * 512 + c;
            float xc = s_x[row][c];
            float xp = (row > 0) ? s_x[row - 1][c] : s_xp0[c];
            float v = fmaf(xp - xc, maa[f] + acc[row], xc);
            if (f == 0) xw[gi] = v;
            else if (f == 1) wsplit(v, kh, kl, gi);
            else if (f == 2) wsplit(v, vh, vl, gi);
            else if (f == 3) wsplit(v, rh, rl, gi);
            else             wsplit(v, gh, gl, gi);
        }
    }
}

// ---------------------------------------------------------------------------
// Weight fp32 -> bf16 hi/lo split
// ---------------------------------------------------------------------------
__global__ void convw_kernel(const float* __restrict__ W,
                             __nv_bfloat16* __restrict__ hi,
                             __nv_bfloat16* __restrict__ lo) {
    int i = blockIdx.x * 256 + threadIdx.x;
    float v = W[i];
    __nv_bfloat16 h = __float2bfloat16(v);
    hi[i] = h;
    lo[i] = __float2bfloat16(v - __bfloat162float(h));
}

// ---------------------------------------------------------------------------
// WKV6 scan. One block per (b,h); warp = output dim i, lane = key dim j.
// ---------------------------------------------------------------------------
__global__ void __launch_bounds__(1024) wkv_kernel(
    const float* __restrict__ r, const float* __restrict__ k,
    const float* __restrict__ v, const float* __restrict__ d,
    const float* __restrict__ u, float* __restrict__ y)
{
    int bh = blockIdx.x;
    int b = bh / HH, h = bh % HH;
    int warp = threadIdx.x >> 5;
    int lane = threadIdx.x & 31;
    __shared__ float ys[32][32];

    float uj = u[h * HSZ + lane];
    float S = 0.f;
    size_t base = ((size_t)b * TT) * CC + h * HSZ;

    for (int t0 = 0; t0 < TT; t0 += 32) {
        #pragma unroll 4
        for (int tt = 0; tt < 32; ++tt) {
            size_t off = base + (size_t)(t0 + tt) * CC;
            float rj = r[off + lane];
            float kj = k[off + lane];
            float dj = d[off + lane];
            float vi = v[off + warp];
            float a  = kj * vi;
            float p  = rj * S + (rj * uj) * a;
            #pragma unroll
            for (int s = 16; s; s >>= 1)
                p += __shfl_xor_sync(0xffffffffu, p, s);
            S = fmaf(dj, S, a);
            if (lane == 0) ys[tt][warp] = p;
        }
        __syncthreads();
        {
            size_t off = base + (size_t)(t0 + warp) * CC;
            y[off + lane] = ys[warp][lane];
        }
        __syncthreads();
    }
}

// ---------------------------------------------------------------------------
// Per-head groupnorm * ln * gate -> bf16 hi/lo split for the Wo GEMM
// ---------------------------------------------------------------------------
__global__ void __launch_bounds__(256) gn_kernel(
    const float* __restrict__ y, const float* __restrict__ gate,
    const float* __restrict__ lnw, const float* __restrict__ lnb,
    __nv_bfloat16* __restrict__ zh, __nv_bfloat16* __restrict__ zl)
{
    int g = blockIdx.x * 8 + (threadIdx.x >> 5);
    int lane = threadIdx.x & 31;
    size_t idx = (size_t)g * 32 + lane;
    float v = y[idx];
    float s = v;
    #pragma unroll
    for (int o = 16; o; o >>= 1) s += __shfl_xor_sync(0xffffffffu, s, o);
    float mu = s * (1.f / 32.f);
    float dv = v - mu;
    float q = dv * dv;
    #pragma unroll
    for (int o = 16; o; o >>= 1) q += __shfl_xor_sync(0xffffffffu, q, o);
    float var = q * (1.f / 32.f);
    float yn = dv * rsqrtf(var + 1e-5f);
    int c = (int)(idx & (CC - 1));
    float z = (yn * lnw[c] + lnb[c]) * gate[idx];
    wsplit(z, zh, zl, idx);
}

// ---------------------------------------------------------------------------
extern "C" void kernel_launch(void* const* d_in, const int* in_sizes, int n_in,
                              void* d_out, int out_size) {
    const float* x      = (const float*)d_in[0];
    const float* tmaa_x = (const float*)d_in[1];
    const float* tmaa_w = (const float*)d_in[2];
    const float* tmaa_k = (const float*)d_in[3];
    const float* tmaa_v = (const float*)d_in[4];
    const float* tmaa_r = (const float*)d_in[5];
    const float* tmaa_g = (const float*)d_in[6];
    const float* w1     = (const float*)d_in[7];   // (C,160)
    const float* w2     = (const float*)d_in[8];   // (5,32,C)
    const float* tdecay = (const float*)d_in[9];   // (C,)
    const float* tdw1   = (const float*)d_in[10];  // (C,64)
    const float* tdw2   = (const float*)d_in[11];  // (64,C)
    const float* faaaa  = (const float*)d_in[12];  // (H,HS)
    const float* Wr     = (const float*)d_in[13];
    const float* Wk     = (const float*)d_in[14];
    const float* Wv     = (const float*)d_in[15];
    const float* Wg     = (const float*)d_in[16];
    const float* Wo     = (const float*)d_in[17];
    const float* lnw    = (const float*)d_in[18];
    const float* lnb    = (const float*)d_in[19];
    float* out = (float*)d_out;

    unsigned char* S;
    cudaGetSymbolAddress((void**)&S, g_scratch);
    float* xxx  = (float*)(S + O_XXX);
    float* mixb = (float*)(S + O_MIX);
    float* xw   = (float*)(S + O_XW);
    float* w64  = (float*)(S + O_W64);
    float* db   = (float*)(S + O_DB);
    float* rb   = (float*)(S + O_RB);
    float* kb   = (float*)(S + O_KB);
    float* vb   = (float*)(S + O_VB);
    float* gb   = (float*)(S + O_GB);
    float* yb   = (float*)(S + O_YB);
    __nv_bfloat16* kh = (__nv_bfloat16*)(S + O_KH);
    __nv_bfloat16* kl = (__nv_bfloat16*)(S + O_KL);
    __nv_bfloat16* vh = (__nv_bfloat16*)(S + O_VH);
    __nv_bfloat16* vl = (__nv_bfloat16*)(S + O_VL);
    __nv_bfloat16* rh = (__nv_bfloat16*)(S + O_RH);
    __nv_bfloat16* rl = (__nv_bfloat16*)(S + O_RL);
    __nv_bfloat16* gh = (__nv_bfloat16*)(S + O_GH);
    __nv_bfloat16* gl = (__nv_bfloat16*)(S + O_GL);
    __nv_bfloat16* zh = (__nv_bfloat16*)(S + O_ZH);
    __nv_bfloat16* zl = (__nv_bfloat16*)(S + O_ZL);
    __nv_bfloat16* wrh = (__nv_bfloat16*)(S + O_WRH);
    __nv_bfloat16* wrl = (__nv_bfloat16*)(S + O_WRL);
    __nv_bfloat16* wkh = (__nv_bfloat16*)(S + O_WKH);
    __nv_bfloat16* wkl = (__nv_bfloat16*)(S + O_WKL);
    __nv_bfloat16* wvh = (__nv_bfloat16*)(S + O_WVH);
    __nv_bfloat16* wvl = (__nv_bfloat16*)(S + O_WVL);
    __nv_bfloat16* wgh = (__nv_bfloat16*)(S + O_WGH);
    __nv_bfloat16* wgl = (__nv_bfloat16*)(S + O_WGL);
    __nv_bfloat16* woh = (__nv_bfloat16*)(S + O_WOH);
    __nv_bfloat16* wol = (__nv_bfloat16*)(S + O_WOL);

    cudaFuncSetAttribute(tgemm_kernel<0>, cudaFuncAttributeMaxDynamicSharedMemorySize, TG_SMEM);
    cudaFuncSetAttribute(tgemm_kernel<2>, cudaFuncAttributeMaxDynamicSharedMemorySize, TG_SMEM);

    // 0) weight splits
    convw_kernel<<<1024, 256>>>(Wr, wrh, wrl);
    convw_kernel<<<1024, 256>>>(Wk, wkh, wkl);
    convw_kernel<<<1024, 256>>>(Wv, wvh, wvl);
    convw_kernel<<<1024, 256>>>(Wg, wgh, wgl);
    convw_kernel<<<1024, 256>>>(Wo, woh, wol);

    // 1) xxx = x + (shift(x)-x)*maa_x
    prep_xxx_kernel<<<(int)(UEL / 256), 256>>>(x, tmaa_x, xxx);

    // 2) mix = tanh(xxx @ w1)   [BT,160]
    sgemm_kernel<false, 1><<<dim3(3, BT / 64), 256>>>(xxx, w1, mixb, nullptr, BT, 160, CC);

    // 3) 5-way mix back-projection + token mixing (16 bt rows per block)
    mix_combine_kernel<<<BT / 16, 512>>>(x, mixb, w2, tmaa_w, tmaa_k, tmaa_v,
                                         tmaa_r, tmaa_g, xw, kh, kl, vh, vl,
                                         rh, rl, gh, gl);

    // 4) projections on tensor cores (mma.sync, split-bf16)
    tgemm_kernel<0><<<dim3(4, BT / 128), 256, TG_SMEM>>>(rh, rl, wrh, wrl, rb);
    tgemm_kernel<0><<<dim3(4, BT / 128), 256, TG_SMEM>>>(kh, kl, wkh, wkl, kb);
    tgemm_kernel<0><<<dim3(4, BT / 128), 256, TG_SMEM>>>(vh, vl, wvh, wvl, vb);
    tgemm_kernel<2><<<dim3(4, BT / 128), 256, TG_SMEM>>>(gh, gl, wgh, wgl, gb);

    // 5) decay MLP: w64 = tanh(xw @ tdw1); d = exp(-exp(tdecay + w64 @ tdw2))
    sgemm_kernel<false, 1><<<dim3(1, BT / 64), 256>>>(xw, tdw1, w64, nullptr, BT, 64, CC);
    sgemm_kernel<false, 3><<<dim3(8, BT / 64), 256>>>(w64, tdw2, db, tdecay, BT, CC, 64);

    // 6) WKV6 scan
    wkv_kernel<<<BQ * HH, 1024>>>(rb, kb, vb, db, faaaa, yb);

    // 7) groupnorm * ln * gate -> z (bf16 split)
    gn_kernel<<<(BT * HH) / 8, 256>>>(yb, gb, lnw, lnb, zh, zl);

    // 8) out = z @ Wo^T (tensor cores)
    tgemm_kernel<0><<<dim3(4, BT / 128), 256, TG_SMEM>>>(zh, zl, woh, wol, out);
}

// round 4
// speedup vs baseline: 1.8235x; 1.0505x over previous
#include <cuda_runtime.h>
#include <cuda_bf16.h>
#include <cstdint>

#define BQ 8
#define TT 2048
#define CC 512
#define HH 16
#define HSZ 32
#define BT (BQ*TT)            // 16384
#define UEL ((size_t)BT*CC)   // 8388608 elements per [B,T,C] buffer

// ---------------------------------------------------------------------------
// Scratch (bytes). One big device array; no allocations anywhere.
// ---------------------------------------------------------------------------
#define SZ_F32   (UEL*4)
#define SZ_BF16  (UEL*2)
#define SZ_MIX   ((size_t)BT*160*4)
#define SZ_W64   ((size_t)BT*64*4)
#define SZ_WBF   ((size_t)CC*CC*2)

#define O_XXX   ((size_t)0)
#define O_MIX   (O_XXX + SZ_F32)
#define O_XW    (O_MIX + SZ_MIX)
#define O_W64   (O_XW + SZ_F32)
#define O_DB    (O_W64 + SZ_W64)
#define O_RB    (O_DB + SZ_F32)
#define O_KB    (O_RB + SZ_F32)
#define O_VB    (O_KB + SZ_F32)
#define O_GB    (O_VB + SZ_F32)
#define O_YB    (O_GB + SZ_F32)
#define O_KH    (O_YB + SZ_F32)
#define O_KL    (O_KH + SZ_BF16)
#define O_VH    (O_KL + SZ_BF16)
#define O_VL    (O_VH + SZ_BF16)
#define O_RH    (O_VL + SZ_BF16)
#define O_RL    (O_RH + SZ_BF16)
#define O_GH    (O_RL + SZ_BF16)
#define O_GL    (O_GH + SZ_BF16)
#define O_ZH    (O_GL + SZ_BF16)
#define O_ZL    (O_ZH + SZ_BF16)
#define O_WRH   (O_ZL + SZ_BF16)
#define O_WRL   (O_WRH + SZ_WBF)
#define O_WKH   (O_WRL + SZ_WBF)
#define O_WKL   (O_WKH + SZ_WBF)
#define O_WVH   (O_WKL + SZ_WBF)
#define O_WVL   (O_WVH + SZ_WBF)
#define O_WGH   (O_WVL + SZ_WBF)
#define O_WGL   (O_WGH + SZ_WBF)
#define O_WOH   (O_WGL + SZ_WBF)
#define O_WOL   (O_WOH + SZ_WBF)
#define SCRATCH_BYTES (O_WOL + SZ_WBF)

__device__ __align__(256) unsigned char g_scratch[SCRATCH_BYTES];

// ---------------------------------------------------------------------------
// mma.sync / cp.async helpers (valid on plain compute_103 / sm_80+)
// ---------------------------------------------------------------------------
__device__ __forceinline__ uint32_t smem_u32(const void* p) {
    uint32_t a;
    asm("{ .reg .u64 t; cvta.to.shared.u64 t, %1; cvt.u32.u64 %0, t; }"
        : "=r"(a) : "l"(p));
    return a;
}

#define LDSM4(r, a) \
    asm volatile("ldmatrix.sync.aligned.m8n8.x4.shared.b16 {%0,%1,%2,%3}, [%4];" \
        : "=r"((r)[0]), "=r"((r)[1]), "=r"((r)[2]), "=r"((r)[3]) : "r"(a))

#define MMA16816(d, a, b0, b1) \
    asm volatile("mma.sync.aligned.m16n8k16.row.col.f32.bf16.bf16.f32 " \
        "{%0,%1,%2,%3}, {%4,%5,%6,%7}, {%8,%9}, {%0,%1,%2,%3};" \
        : "+f"((d)[0]), "+f"((d)[1]), "+f"((d)[2]), "+f"((d)[3]) \
        : "r"((a)[0]), "r"((a)[1]), "r"((a)[2]), "r"((a)[3]), "r"(b0), "r"(b1))

#define CP_ASYNC16(dst, src) \
    asm volatile("cp.async.cg.shared.global [%0], [%1], 16;" :: "r"(dst), "l"(src))
#define CP_COMMIT() asm volatile("cp.async.commit_group;" ::: "memory")
#define CP_WAIT(n)  asm volatile("cp.async.wait_group %0;" :: "n"(n) : "memory")

// ---------------------------------------------------------------------------
// Pipelined tensor-core GEMM: C[M,512] = epi(A @ W^T), split bf16 (hi/lo),
// 3 terms: Ah*Bh + Ah*Bl + Al*Bh. Tile 128x128, K-chunk 32, cp.async 2-stage.
// smem rows: 32 bf16 = 64B data padded to 80B -> (5r+g) mod 8 covers all
// bank groups => conflict-free ldmatrix. Tile 128*80 = 10240B.
// Stage = 4 tiles = 40960B; 2 stages = 81920B => 2 blocks/SM.
// EPI: 0 none, 2 silu.
// ---------------------------------------------------------------------------
#define TROWB 80
#define TTILE (128*TROWB)     // 10240
#define TSTAGE (4*TTILE)      // 40960
#define TG_SMEM (2*TSTAGE)    // 81920

__device__ __forceinline__ void tg_stage_loads(
    uint32_t smb, int stage,
    const __nv_bfloat16* __restrict__ Ah, const __nv_bfloat16* __restrict__ Al,
    const __nv_bfloat16* __restrict__ Bh, const __nv_bfloat16* __restrict__ Bl,
    int bm, int bn, int k0, int tid)
{
    uint32_t sbase = smb + stage * TSTAGE;
    #pragma unroll
    for (int m = 0; m < 4; ++m) {
        const __nv_bfloat16* G = (m == 0) ? Ah : (m == 1) ? Al : (m == 2) ? Bh : Bl;
        int rbase = (m < 2) ? bm : bn;
        #pragma unroll
        for (int it = 0; it < 2; ++it) {
            int idx = it * 256 + tid;          // 0..511
            int row = idx >> 2, g = idx & 3;
            uint32_t d = sbase + m * TTILE + row * TROWB + g * 16;
            const void* src = G + (size_t)(rbase + row) * 512 + k0 + g * 8;
            CP_ASYNC16(d, src);
        }
    }
}

template<int EPI>
__global__ void __launch_bounds__(256, 2)
tgemm_kernel(const __nv_bfloat16* __restrict__ Ah, const __nv_bfloat16* __restrict__ Al,
             const __nv_bfloat16* __restrict__ Bh, const __nv_bfloat16* __restrict__ Bl,
             float* __restrict__ C)
{
    extern __shared__ unsigned char sm[];
    uint32_t smb = smem_u32(sm);
    int tid = threadIdx.x;
    int wid = tid >> 5, lane = tid & 31;
    int bm = blockIdx.y * 128, bn = blockIdx.x * 128;
    int wm = (wid & 3) * 32, wn = (wid >> 2) * 64;

    float acc[2][8][4];
    #pragma unroll
    for (int i = 0; i < 2; ++i)
        #pragma unroll
        for (int j = 0; j < 8; ++j)
            #pragma unroll
            for (int q = 0; q < 4; ++q) acc[i][j][q] = 0.f;

    int mat = lane >> 3, r8 = lane & 7;
    int lrow = (mat & 1) * 8 + r8;    // row within 16-row tile
    int lkb  = (mat >> 1) * 16;       // byte offset within 32B k16 strip

    // prologue: stage chunk 0
    tg_stage_loads(smb, 0, Ah, Al, Bh, Bl, bm, bn, 0, tid);
    CP_COMMIT();

    for (int ch = 0; ch < 16; ++ch) {
        if (ch + 1 < 16) {
            tg_stage_loads(smb, (ch + 1) & 1, Ah, Al, Bh, Bl, bm, bn, (ch + 1) * 32, tid);
            CP_COMMIT();
            CP_WAIT(1);
        } else {
            CP_WAIT(0);
        }
        __syncthreads();

        uint32_t sbase = smb + (ch & 1) * TSTAGE;
        #pragma unroll
        for (int ks = 0; ks < 2; ++ks) {
            uint32_t ah[2][4], al[2][4];
            #pragma unroll
            for (int mt = 0; mt < 2; ++mt) {
                uint32_t ra = sbase + (wm + mt * 16 + lrow) * TROWB + ks * 32 + lkb;
                LDSM4(ah[mt], ra);
                LDSM4(al[mt], ra + TTILE);
            }
            #pragma unroll
            for (int nt = 0; nt < 4; ++nt) {
                uint32_t rb = sbase + 2 * TTILE + (wn + nt * 16 + lrow) * TROWB + ks * 32 + lkb;
                uint32_t bh4[4], bl4[4];
                LDSM4(bh4, rb);
                LDSM4(bl4, rb + TTILE);
                #pragma unroll
                for (int mt = 0; mt < 2; ++mt) {
                    MMA16816(acc[mt][nt*2+0], ah[mt], bh4[0], bh4[2]);
                    MMA16816(acc[mt][nt*2+1], ah[mt], bh4[1], bh4[3]);
                    MMA16816(acc[mt][nt*2+0], ah[mt], bl4[0], bl4[2]);
                    MMA16816(acc[mt][nt*2+1], ah[mt], bl4[1], bl4[3]);
                    MMA16816(acc[mt][nt*2+0], al[mt], bh4[0], bh4[2]);
                    MMA16816(acc[mt][nt*2+1], al[mt], bh4[1], bh4[3]);
                }
            }
        }
        __syncthreads();
    }

    // epilogue: direct stores
    int r0 = lane >> 2, c0 = (lane & 3) * 2;
    #pragma unroll
    for (int mt = 0; mt < 2; ++mt) {
        #pragma unroll
        for (int nt = 0; nt < 4; ++nt) {
            #pragma unroll
            for (int s = 0; s < 2; ++s) {
                float* a4 = acc[mt][nt*2+s];
                int col = bn + wn + nt * 16 + s * 8 + c0;
                int row = bm + wm + mt * 16 + r0;
                float v0 = a4[0], v1 = a4[1], v2 = a4[2], v3 = a4[3];
                if (EPI == 2) {
                    v0 = v0 / (1.f + __expf(-v0));
                    v1 = v1 / (1.f + __expf(-v1));
                    v2 = v2 / (1.f + __expf(-v2));
                    v3 = v3 / (1.f + __expf(-v3));
                }
                *reinterpret_cast<float2*>(C + (size_t)row * 512 + col)       = make_float2(v0, v1);
                *reinterpret_cast<float2*>(C + (size_t)(row + 8) * 512 + col) = make_float2(v2, v3);
            }
        }
    }
}

// ---------------------------------------------------------------------------
// Elementwise: xxx = x + (xshift - x) * time_maa_x
// ---------------------------------------------------------------------------
__global__ void prep_xxx_kernel(const float* __restrict__ x,
                                const float* __restrict__ tmx,
                                float* __restrict__ xxx) {
    size_t i = (size_t)blockIdx.x * blockDim.x + threadIdx.x;
    int c = (int)(i & (CC - 1));
    int t = (int)((i >> 9) & (TT - 1));
    float xv = x[i];
    float xp = (t > 0) ? x[i - CC] : 0.f;
    xxx[i] = xv + (xp - xv) * tmx[c];
}

// ---------------------------------------------------------------------------
// SIMT SGEMM (small GEMMs: mix 160-wide, decay MLP)
// ---------------------------------------------------------------------------
template<bool BT_MAJOR, int EPI>
__global__ void __launch_bounds__(256) sgemm_kernel(
    const float* __restrict__ A, const float* __restrict__ Bm,
    float* __restrict__ Cout, const float* __restrict__ bias,
    int M, int N, int K)
{
    __shared__ float As[16][65];
    __shared__ float Bs[16][65];
    int tid = threadIdx.x;
    int bm = blockIdx.y * 64;
    int bn = blockIdx.x * 64;
    int tx = tid & 15, ty = tid >> 4;
    float acc[4][4] = {};
    int arow = tid >> 2, aseg = tid & 3;

    for (int k0 = 0; k0 < K; k0 += 16) {
        float4 a4 = *reinterpret_cast<const float4*>(
            A + (size_t)(bm + arow) * K + k0 + aseg * 4);
        As[aseg*4+0][arow] = a4.x; As[aseg*4+1][arow] = a4.y;
        As[aseg*4+2][arow] = a4.z; As[aseg*4+3][arow] = a4.w;

        if (BT_MAJOR) {
            int n = tid >> 2, seg = tid & 3;
            float4 b4 = make_float4(0.f, 0.f, 0.f, 0.f);
            if (bn + n < N)
                b4 = *reinterpret_cast<const float4*>(
                    Bm + (size_t)(bn + n) * K + k0 + seg * 4);
            Bs[seg*4+0][n] = b4.x; Bs[seg*4+1][n] = b4.y;
            Bs[seg*4+2][n] = b4.z; Bs[seg*4+3][n] = b4.w;
        } else {
            int kk = tid >> 4, nb = (tid & 15) * 4;
            float4 b4 = make_float4(0.f, 0.f, 0.f, 0.f);
            if (bn + nb < N)
                b4 = *reinterpret_cast<const float4*>(
                    Bm + (size_t)(k0 + kk) * N + bn + nb);
            Bs[kk][nb+0] = b4.x; Bs[kk][nb+1] = b4.y;
            Bs[kk][nb+2] = b4.z; Bs[kk][nb+3] = b4.w;
        }
        __syncthreads();

        #pragma unroll
        for (int kk = 0; kk < 16; ++kk) {
            float ar[4], br[4];
            #pragma unroll
            for (int q = 0; q < 4; ++q) ar[q] = As[kk][ty*4 + q];
            #pragma unroll
            for (int p = 0; p < 4; ++p) br[p] = Bs[kk][tx*4 + p];
            #pragma unroll
            for (int q = 0; q < 4; ++q)
                #pragma unroll
                for (int p = 0; p < 4; ++p)
                    acc[q][p] = fmaf(ar[q], br[p], acc[q][p]);
        }
        __syncthreads();
    }

    #pragma unroll
    for (int q = 0; q < 4; ++q) {
        int row = bm + ty*4 + q;
        #pragma unroll
        for (int p = 0; p < 4; ++p) {
            int col = bn + tx*4 + p;
            if (col < N) {
                float v = acc[q][p];
                if (EPI == 1) v = tanhf(v);
                else if (EPI == 3) v = __expf(-__expf(bias[col] + v));
                Cout[(size_t)row * N + col] = v;
            }
        }
    }
}

// ---------------------------------------------------------------------------
// split helper
// ---------------------------------------------------------------------------
__device__ __forceinline__ void wsplit(float v, __nv_bfloat16* hi, __nv_bfloat16* lo, size_t i) {
    __nv_bfloat16 h = __float2bfloat16(v);
    hi[i] = h;
    lo[i] = __float2bfloat16(v - __bfloat162float(h));
}

// ---------------------------------------------------------------------------
// mix back-projection + 5-way token mix. Block = 16 bt rows x 512 c.
// ---------------------------------------------------------------------------
__global__ void __launch_bounds__(512) mix_combine_kernel(
    const float* __restrict__ x, const float* __restrict__ mix,
    const float* __restrict__ W2,
    const float* __restrict__ maaw, const float* __restrict__ maak,
    const float* __restrict__ maav, const float* __restrict__ maar,
    const float* __restrict__ maag,
    float* __restrict__ xw,
    __nv_bfloat16* __restrict__ kh, __nv_bfloat16* __restrict__ kl,
    __nv_bfloat16* __restrict__ vh, __nv_bfloat16* __restrict__ vl,
    __nv_bfloat16* __restrict__ rh, __nv_bfloat16* __restrict__ rl,
    __nv_bfloat16* __restrict__ gh, __nv_bfloat16* __restrict__ gl)
{
    __shared__ float s_mix[16][160];
    __shared__ float s_x[16][512];
    __shared__ float s_xp0[512];
    int bt0 = blockIdx.x * 16;
    int c = threadIdx.x;

    for (int i = threadIdx.x; i < 16 * 160; i += 512)
        s_mix[i / 160][i % 160] = mix[(size_t)bt0 * 160 + i];
    #pragma unroll
    for (int row = 0; row < 16; ++row)
        s_x[row][c] = x[(size_t)(bt0 + row) * 512 + c];
    s_xp0[c] = (bt0 & (TT - 1)) ? x[(size_t)(bt0 - 1) * 512 + c] : 0.f;
    __syncthreads();

    float maa[5];
    maa[0] = maaw[c]; maa[1] = maak[c]; maa[2] = maav[c];
    maa[3] = maar[c]; maa[4] = maag[c];

    #pragma unroll
    for (int f = 0; f < 5; ++f) {
        float acc[16];
        #pragma unroll
        for (int row = 0; row < 16; ++row) acc[row] = 0.f;
        #pragma unroll 8
        for (int dd = 0; dd < 32; ++dd) {
            float w = W2[(size_t)(f * 32 + dd) * 512 + c];
            #pragma unroll
            for (int row = 0; row < 16; ++row)
                acc[row] = fmaf(s_mix[row][f * 32 + dd], w, acc[row]);
        }
        #pragma unroll
        for (int row = 0; row < 16; ++row) {
            size_t gi = (size_t)(bt0 + row) * 512 + c;
            float xc = s_x[row][c];
            float xp = (row > 0) ? s_x[row - 1][c] : s_xp0[c];
            float v = fmaf(xp - xc, maa[f] + acc[row], xc);
            if (f == 0) xw[gi] = v;
            else if (f == 1) wsplit(v, kh, kl, gi);
            else if (f == 2) wsplit(v, vh, vl, gi);
            else if (f == 3) wsplit(v, rh, rl, gi);
            else             wsplit(v, gh, gl, gi);
        }
    }
}

// ---------------------------------------------------------------------------
// All weight fp32 -> bf16 hi/lo splits in one launch (grid.y = which weight)
// ---------------------------------------------------------------------------
__global__ void convw_all_kernel(const float* __restrict__ W0, const float* __restrict__ W1,
                                 const float* __restrict__ W2, const float* __restrict__ W3,
                                 const float* __restrict__ W4,
                                 __nv_bfloat16* __restrict__ H0, __nv_bfloat16* __restrict__ L0,
                                 __nv_bfloat16* __restrict__ H1, __nv_bfloat16* __restrict__ L1,
                                 __nv_bfloat16* __restrict__ H2, __nv_bfloat16* __restrict__ L2,
                                 __nv_bfloat16* __restrict__ H3, __nv_bfloat16* __restrict__ L3,
                                 __nv_bfloat16* __restrict__ H4, __nv_bfloat16* __restrict__ L4)
{
    int w = blockIdx.y;
    const float* W = (w == 0) ? W0 : (w == 1) ? W1 : (w == 2) ? W2 : (w == 3) ? W3 : W4;
    __nv_bfloat16* H = (w == 0) ? H0 : (w == 1) ? H1 : (w == 2) ? H2 : (w == 3) ? H3 : H4;
    __nv_bfloat16* L = (w == 0) ? L0 : (w == 1) ? L1 : (w == 2) ? L2 : (w == 3) ? L3 : L4;
    int i = blockIdx.x * 256 + threadIdx.x;
    float v = W[i];
    __nv_bfloat16 h = __float2bfloat16(v);
    H[i] = h;
    L[i] = __float2bfloat16(v - __bfloat162float(h));
}

// ---------------------------------------------------------------------------
// WKV6 scan. One block per (b,h); warp = output dim i, lane = key dim j.
// ---------------------------------------------------------------------------
__global__ void __launch_bounds__(1024) wkv_kernel(
    const float* __restrict__ r, const float* __restrict__ k,
    const float* __restrict__ v, const float* __restrict__ d,
    const float* __restrict__ u, float* __restrict__ y)
{
    int bh = blockIdx.x;
    int b = bh / HH, h = bh % HH;
    int warp = threadIdx.x >> 5;
    int lane = threadIdx.x & 31;
    __shared__ float ys[32][32];

    float uj = u[h * HSZ + lane];
    float S = 0.f;
    size_t base = ((size_t)b * TT) * CC + h * HSZ;

    for (int t0 = 0; t0 < TT; t0 += 32) {
        #pragma unroll 4
        for (int tt = 0; tt < 32; ++tt) {
            size_t off = base + (size_t)(t0 + tt) * CC;
            float rj = r[off + lane];
            float kj = k[off + lane];
            float dj = d[off + lane];
            float vi = v[off + warp];
            float a  = kj * vi;
            float p  = rj * S + (rj * uj) * a;
            #pragma unroll
            for (int s = 16; s; s >>= 1)
                p += __shfl_xor_sync(0xffffffffu, p, s);
            S = fmaf(dj, S, a);
            if (lane == 0) ys[tt][warp] = p;
        }
        __syncthreads();
        {
            size_t off = base + (size_t)(t0 + warp) * CC;
            y[off + lane] = ys[warp][lane];
        }
        __syncthreads();
    }
}

// ---------------------------------------------------------------------------
// Per-head groupnorm * ln * gate -> bf16 hi/lo split for the Wo GEMM
// ---------------------------------------------------------------------------
__global__ void __launch_bounds__(256) gn_kernel(
    const float* __restrict__ y, const float* __restrict__ gate,
    const float* __restrict__ lnw, const float* __restrict__ lnb,
    __nv_bfloat16* __restrict__ zh, __nv_bfloat16* __restrict__ zl)
{
    int g = blockIdx.x * 8 + (threadIdx.x >> 5);
    int lane = threadIdx.x & 31;
    size_t idx = (size_t)g * 32 + lane;
    float v = y[idx];
    float s = v;
    #pragma unroll
    for (int o = 16; o; o >>= 1) s += __shfl_xor_sync(0xffffffffu, s, o);
    float mu = s * (1.f / 32.f);
    float dv = v - mu;
    float q = dv * dv;
    #pragma unroll
    for (int o = 16; o; o >>= 1) q += __shfl_xor_sync(0xffffffffu, q, o);
    float var = q * (1.f / 32.f);
    float yn = dv * rsqrtf(var + 1e-5f);
    int c = (int)(idx & (CC - 1));
    float z = (yn * lnw[c] + lnb[c]) * gate[idx];
    wsplit(z, zh, zl, idx);
}

// ---------------------------------------------------------------------------
extern "C" void kernel_launch(void* const* d_in, const int* in_sizes, int n_in,
                              void* d_out, int out_size) {
    const float* x      = (const float*)d_in[0];
    const float* tmaa_x = (const float*)d_in[1];
    const float* tmaa_w = (const float*)d_in[2];
    const float* tmaa_k = (const float*)d_in[3];
    const float* tmaa_v = (const float*)d_in[4];
    const float* tmaa_r = (const float*)d_in[5];
    const float* tmaa_g = (const float*)d_in[6];
    const float* w1     = (const float*)d_in[7];   // (C,160)
    const float* w2     = (const float*)d_in[8];   // (5,32,C)
    const float* tdecay = (const float*)d_in[9];   // (C,)
    const float* tdw1   = (const float*)d_in[10];  // (C,64)
    const float* tdw2   = (const float*)d_in[11];  // (64,C)
    const float* faaaa  = (const float*)d_in[12];  // (H,HS)
    const float* Wr     = (const float*)d_in[13];
    const float* Wk     = (const float*)d_in[14];
    const float* Wv     = (const float*)d_in[15];
    const float* Wg     = (const float*)d_in[16];
    const float* Wo     = (const float*)d_in[17];
    const float* lnw    = (const float*)d_in[18];
    const float* lnb    = (const float*)d_in[19];
    float* out = (float*)d_out;

    unsigned char* S;
    cudaGetSymbolAddress((void**)&S, g_scratch);
    float* xxx  = (float*)(S + O_XXX);
    float* mixb = (float*)(S + O_MIX);
    float* xw   = (float*)(S + O_XW);
    float* w64  = (float*)(S + O_W64);
    float* db   = (float*)(S + O_DB);
    float* rb   = (float*)(S + O_RB);
    float* kb   = (float*)(S + O_KB);
    float* vb   = (float*)(S + O_VB);
    float* gb   = (float*)(S + O_GB);
    float* yb   = (float*)(S + O_YB);
    __nv_bfloat16* kh = (__nv_bfloat16*)(S + O_KH);
    __nv_bfloat16* kl = (__nv_bfloat16*)(S + O_KL);
    __nv_bfloat16* vh = (__nv_bfloat16*)(S + O_VH);
    __nv_bfloat16* vl = (__nv_bfloat16*)(S + O_VL);
    __nv_bfloat16* rh = (__nv_bfloat16*)(S + O_RH);
    __nv_bfloat16* rl = (__nv_bfloat16*)(S + O_RL);
    __nv_bfloat16* gh = (__nv_bfloat16*)(S + O_GH);
    __nv_bfloat16* gl = (__nv_bfloat16*)(S + O_GL);
    __nv_bfloat16* zh = (__nv_bfloat16*)(S + O_ZH);
    __nv_bfloat16* zl = (__nv_bfloat16*)(S + O_ZL);
    __nv_bfloat16* wrh = (__nv_bfloat16*)(S + O_WRH);
    __nv_bfloat16* wrl = (__nv_bfloat16*)(S + O_WRL);
    __nv_bfloat16* wkh = (__nv_bfloat16*)(S + O_WKH);
    __nv_bfloat16* wkl = (__nv_bfloat16*)(S + O_WKL);
    __nv_bfloat16* wvh = (__nv_bfloat16*)(S + O_WVH);
    __nv_bfloat16* wvl = (__nv_bfloat16*)(S + O_WVL);
    __nv_bfloat16* wgh = (__nv_bfloat16*)(S + O_WGH);
    __nv_bfloat16* wgl = (__nv_bfloat16*)(S + O_WGL);
    __nv_bfloat16* woh = (__nv_bfloat16*)(S + O_WOH);
    __nv_bfloat16* wol = (__nv_bfloat16*)(S + O_WOL);

    cudaFuncSetAttribute(tgemm_kernel<0>, cudaFuncAttributeMaxDynamicSharedMemorySize, TG_SMEM);
    cudaFuncSetAttribute(tgemm_kernel<2>, cudaFuncAttributeMaxDynamicSharedMemorySize, TG_SMEM);

    // 0) weight splits, one launch
    convw_all_kernel<<<dim3(1024, 5), 256>>>(Wr, Wk, Wv, Wg, Wo,
                                             wrh, wrl, wkh, wkl, wvh, wvl,
                                             wgh, wgl, woh, wol);

    // 1) xxx = x + (shift(x)-x)*maa_x
    prep_xxx_kernel<<<(int)(UEL / 256), 256>>>(x, tmaa_x, xxx);

    // 2) mix = tanh(xxx @ w1)   [BT,160]
    sgemm_kernel<false, 1><<<dim3(3, BT / 64), 256>>>(xxx, w1, mixb, nullptr, BT, 160, CC);

    // 3) 5-way mix back-projection + token mixing (16 bt rows per block)
    mix_combine_kernel<<<BT / 16, 512>>>(x, mixb, w2, tmaa_w, tmaa_k, tmaa_v,
                                         tmaa_r, tmaa_g, xw, kh, kl, vh, vl,
                                         rh, rl, gh, gl);

    // 4) projections on tensor cores (mma.sync, split-bf16, cp.async pipeline)
    tgemm_kernel<0><<<dim3(4, BT / 128), 256, TG_SMEM>>>(rh, rl, wrh, wrl, rb);
    tgemm_kernel<0><<<dim3(4, BT / 128), 256, TG_SMEM>>>(kh, kl, wkh, wkl, kb);
    tgemm_kernel<0><<<dim3(4, BT / 128), 256, TG_SMEM>>>(vh, vl, wvh, wvl, vb);
    tgemm_kernel<2><<<dim3(4, BT / 128), 256, TG_SMEM>>>(gh, gl, wgh, wgl, gb);

    // 5) decay MLP: w64 = tanh(xw @ tdw1); d = exp(-exp(tdecay + w64 @ tdw2))
    sgemm_kernel<false, 1><<<dim3(1, BT / 64), 256>>>(xw, tdw1, w64, nullptr, BT, 64, CC);
    sgemm_kernel<false, 3><<<dim3(8, BT / 64), 256>>>(w64, tdw2, db, tdecay, BT, CC, 64);

    // 6) WKV6 scan
    wkv_kernel<<<BQ * HH, 1024>>>(rb, kb, vb, db, faaaa, yb);

    // 7) groupnorm * ln * gate -> z (bf16 split)
    gn_kernel<<<(BT * HH) / 8, 256>>>(yb, gb, lnw, lnb, zh, zl);

    // 8) out = z @ Wo^T (tensor cores)
    tgemm_kernel<0><<<dim3(4, BT / 128), 256, TG_SMEM>>>(zh, zl, woh, wol, out);
}